// round 2
// baseline (speedup 1.0000x reference)
#include <cuda_runtime.h>
#include <math.h>

#define BATCH 4096
#define HID   256
#define SEQN  24
#define BOARD 361

// ---------------- device scratch (no allocs allowed) ----------------
__device__ float g_Wt0[2 * BOARD * 1024];                       // transposed W_ih0: [d][pos][1024]
__device__ float g_bias0[2 * 1024];                             // b_ih0 + b_hh0
__device__ float g_bias1[2 * 1024];                             // b_ih1 + b_hh1
__device__ float g_c[(size_t)4 * BATCH * HID];                  // cell state, idx = 2*layer + d
__device__ float g_X0[(size_t)SEQN * BATCH * 2 * HID];          // layer-0 outputs [t][b][d*H + n]

// ---------------- prep: transpose W_ih0, fold biases, init c ----------------
__global__ void prep_kernel(const float* __restrict__ Wih0,
                            const float* __restrict__ bih0, const float* __restrict__ bhh0,
                            const float* __restrict__ bih1, const float* __restrict__ bhh1,
                            const float* __restrict__ c0)
{
    int tid = blockIdx.x * blockDim.x + threadIdx.x;
    int stride = gridDim.x * blockDim.x;

    const int NT = 2 * BOARD * 1024;
    for (int i = tid; i < NT; i += stride) {
        int d = i / (BOARD * 1024);
        int rem = i - d * (BOARD * 1024);
        int p = rem >> 10;
        int j = rem & 1023;
        g_Wt0[i] = Wih0[(size_t)d * 1024 * BOARD + (size_t)j * BOARD + p];
    }
    for (int i = tid; i < 2048; i += stride) g_bias0[i] = bih0[i] + bhh0[i];
    for (int i = tid; i < 2048; i += stride) g_bias1[i] = bih1[i] + bhh1[i];

    const int NC = 4 * BATCH * HID;
    for (int i = tid; i < NC; i += stride) g_c[i] = c0[i];
}

// ---------------- helpers ----------------
__device__ __forceinline__ float sigf(float x) { return 1.0f / (1.0f + expf(-x)); }

// Accumulate gates[b][gate*256 + n0 + tx] += sum_k A[b][k] * W[j][k]
// Block tile: 32 b-rows x 64 units x 4 gates. Thread tile: 8 m x 4 gates.
template <int KCH>
__device__ __forceinline__ void mm_acc(const float* __restrict__ A, int lda,
                                       const float* __restrict__ W, int ldw,
                                       int tx, int ty, int tid, int n0,
                                       float acc[4][8],
                                       float (* __restrict__ w_sm)[36],
                                       float (* __restrict__ h_sm)[36])
{
#pragma unroll 1
    for (int c = 0; c < KCH; ++c) {
        const int k0 = c * 32;
        __syncthreads();
        // W tile: 256 rows (gate*64 + nl) x 32 k, 8 float4 per thread, coalesced
#pragma unroll
        for (int i = 0; i < 8; ++i) {
            int idx = i * 256 + tid;
            int r   = idx >> 3;
            int kk  = idx & 7;
            int j   = ((r >> 6) << 8) + n0 + (r & 63);
            float4 v = *reinterpret_cast<const float4*>(W + (size_t)j * ldw + k0 + kk * 4);
            *reinterpret_cast<float4*>(&w_sm[r][kk * 4]) = v;
        }
        // A tile: 32 rows x 32 k, 1 float4 per thread
        {
            int r  = tid >> 3;
            int kk = tid & 7;
            float4 v = *reinterpret_cast<const float4*>(A + (size_t)r * lda + k0 + kk * 4);
            *reinterpret_cast<float4*>(&h_sm[r][kk * 4]) = v;
        }
        __syncthreads();
#pragma unroll
        for (int k = 0; k < 32; k += 4) {
            float4 wv0 = *reinterpret_cast<const float4*>(&w_sm[tx][k]);
            float4 wv1 = *reinterpret_cast<const float4*>(&w_sm[64 + tx][k]);
            float4 wv2 = *reinterpret_cast<const float4*>(&w_sm[128 + tx][k]);
            float4 wv3 = *reinterpret_cast<const float4*>(&w_sm[192 + tx][k]);
#pragma unroll
            for (int mi = 0; mi < 8; ++mi) {
                float4 hv = *reinterpret_cast<const float4*>(&h_sm[ty * 8 + mi][k]);
                acc[0][mi] += wv0.x * hv.x; acc[0][mi] += wv0.y * hv.y;
                acc[0][mi] += wv0.z * hv.z; acc[0][mi] += wv0.w * hv.w;
                acc[1][mi] += wv1.x * hv.x; acc[1][mi] += wv1.y * hv.y;
                acc[1][mi] += wv1.z * hv.z; acc[1][mi] += wv1.w * hv.w;
                acc[2][mi] += wv2.x * hv.x; acc[2][mi] += wv2.y * hv.y;
                acc[2][mi] += wv2.z * hv.z; acc[2][mi] += wv2.w * hv.w;
                acc[3][mi] += wv3.x * hv.x; acc[3][mi] += wv3.y * hv.y;
                acc[3][mi] += wv3.z * hv.z; acc[3][mi] += wv3.w * hv.w;
            }
        }
    }
}

// ---------------- one timestep of one layer (both cells via blockIdx.z) ----------------
__global__ void __launch_bounds__(256) lstm_step(
    int layer, int t,
    const int*   __restrict__ data,
    const float* __restrict__ h0,
    const float* __restrict__ Whh0,
    const float* __restrict__ Wih1,
    const float* __restrict__ Whh1,
    float*       __restrict__ out)
{
    __shared__ float w_sm[256][36];
    __shared__ float h_sm[32][36];

    const int tx  = threadIdx.x;            // 0..63 : unit within 64-wide n-tile
    const int ty  = threadIdx.y;            // 0..3  : m-group (8 rows each)
    const int tid = ty * 64 + tx;
    const int n0  = blockIdx.x * 64;        // unit tile base (0..255)
    const int b0  = blockIdx.y * 32;        // batch tile base
    const int d   = blockIdx.z;             // cell index within layer

    float acc[4][8];
#pragma unroll
    for (int g = 0; g < 4; ++g)
#pragma unroll
        for (int m = 0; m < 8; ++m) acc[g][m] = 0.f;

    // recurrent input h_{t-1}
    const float* hprev;
    int hlda;
    if (layer == 0) {
        if (t == 0) { hprev = h0 + ((size_t)d * BATCH + b0) * HID;                    hlda = HID; }
        else        { hprev = g_X0 + ((size_t)(t - 1) * BATCH + b0) * (2 * HID) + d * HID; hlda = 2 * HID; }
    } else {
        if (t == 0) { hprev = h0 + ((size_t)(2 + d) * BATCH + b0) * HID;              hlda = HID; }
        else        { hprev = out + (size_t)b0 * SEQN * 2 * HID + (size_t)(t - 1) * 2 * HID + d * HID; hlda = SEQN * 2 * HID; }
    }

    if (layer == 1) {
        // input GEMM: X0[t] (4096 x 512) @ W_ih1[d].T
        const float* A = g_X0 + ((size_t)t * BATCH + b0) * (2 * HID);
        mm_acc<16>(A, 2 * HID, Wih1 + (size_t)d * 4 * HID * (2 * HID), 2 * HID,
                   tx, ty, tid, n0, acc, w_sm, h_sm);
    }
    {
        // recurrent GEMM: h_prev (4096 x 256) @ W_hh.T
        const float* W = (layer == 0 ? Whh0 : Whh1) + (size_t)d * 4 * HID * HID;
        mm_acc<8>(hprev, hlda, W, HID, tx, ty, tid, n0, acc, w_sm, h_sm);
    }

    const float* bias = (layer == 0 ? g_bias0 : g_bias1) + d * 4 * HID;
    const float bi = bias[0 * HID + n0 + tx];
    const float bf = bias[1 * HID + n0 + tx];
    const float bg = bias[2 * HID + n0 + tx];
    const float bo = bias[3 * HID + n0 + tx];

#pragma unroll
    for (int mi = 0; mi < 8; ++mi) {
        const int b = b0 + ty * 8 + mi;
        float gi = acc[0][mi] + bi;
        float gf = acc[1][mi] + bf;
        float gg = acc[2][mi] + bg;
        float go = acc[3][mi] + bo;

        if (layer == 0) {
            // one-hot input GEMM == row gather of transposed W_ih0
            int pos = data[b * SEQN + t];
            if (pos >= 0) {
                const float* wr = g_Wt0 + ((size_t)d * BOARD + pos) * 1024 + n0 + tx;
                gi += wr[0 * HID];
                gf += wr[1 * HID];
                gg += wr[2 * HID];
                go += wr[3 * HID];
            }
        }

        const size_t ci = ((size_t)(2 * layer + d) * BATCH + b) * HID + n0 + tx;
        float cold = g_c[ci];
        float cn = sigf(gf) * cold + sigf(gi) * tanhf(gg);
        float hn = sigf(go) * tanhf(cn);
        g_c[ci] = cn;

        if (layer == 0)
            g_X0[((size_t)t * BATCH + b) * (2 * HID) + d * HID + n0 + tx] = hn;
        else
            out[((size_t)b * SEQN + t) * (2 * HID) + d * HID + n0 + tx] = hn;
    }
}

// ---------------- launch ----------------
extern "C" void kernel_launch(void* const* d_in, const int* in_sizes, int n_in,
                              void* d_out, int out_size)
{
    const int*   data = (const int*)  d_in[0];
    const float* h0   = (const float*)d_in[1];
    const float* c0   = (const float*)d_in[2];
    const float* Wih0 = (const float*)d_in[3];
    const float* Whh0 = (const float*)d_in[4];
    const float* bih0 = (const float*)d_in[5];
    const float* bhh0 = (const float*)d_in[6];
    const float* Wih1 = (const float*)d_in[7];
    const float* Whh1 = (const float*)d_in[8];
    const float* bih1 = (const float*)d_in[9];
    const float* bhh1 = (const float*)d_in[10];
    float* out = (float*)d_out;

    prep_kernel<<<1024, 256>>>(Wih0, bih0, bhh0, bih1, bhh1, c0);

    dim3 grid(4, BATCH / 32, 2);   // n-tiles x b-tiles x cells
    dim3 blk(64, 4, 1);
    for (int t = 0; t < SEQN; ++t)
        lstm_step<<<grid, blk>>>(0, t, data, h0, Whh0, Wih1, Whh1, out);
    for (int t = 0; t < SEQN; ++t)
        lstm_step<<<grid, blk>>>(1, t, data, h0, Whh0, Wih1, Whh1, out);
}

// round 9
// speedup vs baseline: 1.5945x; 1.5945x over previous
#include <cuda_runtime.h>
#include <cuda_bf16.h>
#include <math.h>
#include <stdint.h>

#define BATCH 4096
#define HID   256
#define SEQN  24
#define BOARD 361

// ---------------- device scratch (statics; no runtime allocs) ----------------
__device__ __nv_bfloat16 g_X0hi[SEQN + 1][BATCH][512];   // layer-0 outputs, hi part (slot 0 = h0)
__device__ __nv_bfloat16 g_X0lo[SEQN + 1][BATCH][512];   // residual part
__device__ __nv_bfloat16 g_H1hi[2][2][BATCH][HID];       // [parity][cell] layer-1 h state
__device__ __nv_bfloat16 g_H1lo[2][2][BATCH][HID];
__device__ __nv_bfloat16 g_W0hi[2][1024][256];           // Whh0, rows reordered j' = 4u+g
__device__ __nv_bfloat16 g_W0lo[2][1024][256];
__device__ __nv_bfloat16 g_W1hi[2][1024][768];           // [Wih1 | Whh1] concat on K, reordered
__device__ __nv_bfloat16 g_W1lo[2][1024][768];
__device__ float g_Wt0r[2][BOARD][1024];                 // transposed+reordered W_ih0 (fp32 gather)
__device__ float g_b0r[2][1024];                         // folded biases, reordered
__device__ float g_b1r[2][1024];
__device__ float g_cT[4][256][BATCH];                    // cell state, transposed [cell][unit][b]

// ---------------- PTX helpers (arch-portable: sm_80+ features only) ----------------
__device__ __forceinline__ uint32_t smem_u32(const void* p) {
    uint32_t a;
    asm("{ .reg .u64 t; cvta.to.shared.u64 t, %1; cvt.u32.u64 %0, t; }" : "=r"(a) : "l"(p));
    return a;
}
__device__ __forceinline__ void cp16(uint32_t dst, const void* src) {
    asm volatile("cp.async.cg.shared.global [%0], [%1], 16;" :: "r"(dst), "l"(src));
}
#define CP_COMMIT() asm volatile("cp.async.commit_group;" ::: "memory")
#define CP_WAIT(n)  asm volatile("cp.async.wait_group %0;" :: "n"(n) : "memory")

__device__ __forceinline__ void ldsm4(uint32_t* r, uint32_t addr) {
    asm volatile("ldmatrix.sync.aligned.m8n8.x4.shared.b16 {%0,%1,%2,%3}, [%4];"
                 : "=r"(r[0]), "=r"(r[1]), "=r"(r[2]), "=r"(r[3]) : "r"(addr));
}
__device__ __forceinline__ void mma16816(float* c, const uint32_t* a, const uint32_t* b) {
    asm volatile("mma.sync.aligned.m16n8k16.row.col.f32.bf16.bf16.f32 "
                 "{%0,%1,%2,%3}, {%4,%5,%6,%7}, {%8,%9}, {%0,%1,%2,%3};"
                 : "+f"(c[0]), "+f"(c[1]), "+f"(c[2]), "+f"(c[3])
                 : "r"(a[0]), "r"(a[1]), "r"(a[2]), "r"(a[3]), "r"(b[0]), "r"(b[1]));
}

__device__ __forceinline__ float sigf(float x) { return 1.0f / (1.0f + expf(-x)); }
__device__ __forceinline__ void split_bf16(float v, __nv_bfloat16& hi, __nv_bfloat16& lo) {
    hi = __float2bfloat16(v);
    lo = __float2bfloat16(v - __bfloat162float(hi));
}

// ---------------- prep: splits, reorders, transposes, state init ----------------
__global__ void prep_kernel(const float* __restrict__ h0, const float* __restrict__ c0,
                            const float* __restrict__ Wih0, const float* __restrict__ Whh0,
                            const float* __restrict__ bih0, const float* __restrict__ bhh0,
                            const float* __restrict__ Wih1, const float* __restrict__ Whh1,
                            const float* __restrict__ bih1, const float* __restrict__ bhh1)
{
    int t0 = blockIdx.x * blockDim.x + threadIdx.x;
    int stride = gridDim.x * blockDim.x;

    for (int i = t0; i < 2 * 1024 * 256; i += stride) {
        int cell = i >> 18, r = (i >> 8) & 1023, k = i & 255;
        int j = (r & 3) * 256 + (r >> 2);
        float v = Whh0[(size_t)cell * 1024 * 256 + (size_t)j * 256 + k];
        split_bf16(v, g_W0hi[cell][r][k], g_W0lo[cell][r][k]);
    }
    for (int i = t0; i < 2 * 1024 * 768; i += stride) {
        int cell = i / (1024 * 768), rem = i - cell * (1024 * 768);
        int r = rem / 768, k = rem - r * 768;
        int j = (r & 3) * 256 + (r >> 2);
        float v = (k < 512) ? Wih1[(size_t)cell * 1024 * 512 + (size_t)j * 512 + k]
                            : Whh1[(size_t)cell * 1024 * 256 + (size_t)j * 256 + (k - 512)];
        split_bf16(v, g_W1hi[cell][r][k], g_W1lo[cell][r][k]);
    }
    for (int i = t0; i < 2 * BOARD * 1024; i += stride) {
        int cell = i / (BOARD * 1024), rem = i - cell * (BOARD * 1024);
        int p = rem >> 10, jp = rem & 1023;
        int j = (jp & 3) * 256 + (jp >> 2);
        g_Wt0r[cell][p][jp] = Wih0[(size_t)cell * 1024 * BOARD + (size_t)j * BOARD + p];
    }
    for (int i = t0; i < 2 * 1024; i += stride) {
        int cell = i >> 10, jp = i & 1023;
        int j = (jp & 3) * 256 + (jp >> 2);
        g_b0r[cell][jp] = bih0[cell * 1024 + j] + bhh0[cell * 1024 + j];
        g_b1r[cell][jp] = bih1[cell * 1024 + j] + bhh1[cell * 1024 + j];
    }
    for (int i = t0; i < 2 * BATCH * HID; i += stride) {
        int cell = i / (BATCH * HID), rem = i - cell * (BATCH * HID);
        int b = rem >> 8, n = rem & 255;
        float v0 = h0[((size_t)cell * BATCH + b) * HID + n];
        split_bf16(v0, g_X0hi[0][b][cell * 256 + n], g_X0lo[0][b][cell * 256 + n]);
        float v1 = h0[((size_t)(2 + cell) * BATCH + b) * HID + n];
        split_bf16(v1, g_H1hi[0][cell][b][n], g_H1lo[0][cell][b][n]);
    }
    for (int i = t0; i < 4 * 256 * BATCH; i += stride) {
        int cl = i / (256 * BATCH), rem = i - cl * (256 * BATCH);
        int n = rem / BATCH, b = rem - n * BATCH;
        g_cT[cl][n][b] = c0[((size_t)cl * BATCH + b) * HID + n];
    }
}

// ---------------- mma.sync LSTM step ----------------
// CTA tile: M=128 batch x N=128 gate-cols (32 units x 4 gates). K chunks of 32 bf16.
// 3-term compensated: Ahi*Bhi + Alo*Bhi + Ahi*Blo, fp32 accum in registers.
// SMEM chunk buffer: [Ahi|Alo|Bhi|Blo] each 128x32 bf16 (8KB), double buffered = 64KB.
// 16B-granule swizzle: seg_phys = seg ^ ((row>>1)&3) -> conflict-free ldmatrix.
#define TILE_B   8192
#define BUF_B    (4 * TILE_B)
#define GP       129
#define SMEM_TOTAL (128 * GP * 4)   // 66048 >= 2*BUF_B

__device__ __forceinline__ uint32_t sw_off(int row, int seg) {
    return (uint32_t)(row * 64 + ((seg ^ ((row >> 1) & 3)) << 4));
}

template <int LAYER>
__device__ __forceinline__ void issue_chunk_loads(int t, int cell, int b0, int jbase,
                                                  int kc, uint32_t sbuf, int tid)
{
    const __nv_bfloat16 *Ah, *Al;
    int apitch, acol;
    if (LAYER == 0) {
        Ah = &g_X0hi[t][0][cell * HID]; Al = &g_X0lo[t][0][cell * HID];
        apitch = 512; acol = kc * 32;
    } else if (kc < 16) {
        Ah = &g_X0hi[t + 1][0][0]; Al = &g_X0lo[t + 1][0][0];
        apitch = 512; acol = kc * 32;
    } else {
        int p = t & 1;
        Ah = &g_H1hi[p][cell][0][0]; Al = &g_H1lo[p][cell][0][0];
        apitch = HID; acol = (kc - 16) * 32;
    }
    const __nv_bfloat16* Bh = LAYER ? &g_W1hi[cell][0][0] : &g_W0hi[cell][0][0];
    const __nv_bfloat16* Bl = LAYER ? &g_W1lo[cell][0][0] : &g_W0lo[cell][0][0];
    const int bpitch = LAYER ? 768 : 256, bcol = kc * 32;

#pragma unroll
    for (int it = 0; it < 8; ++it) {
        int id   = it * 256 + tid;
        int tile = id >> 9;
        int rem  = id & 511;
        int row  = rem >> 2;
        int seg  = rem & 3;
        const __nv_bfloat16* src;
        int pitch, col, grow;
        if (tile == 0)      { src = Ah; pitch = apitch; col = acol; grow = b0 + row; }
        else if (tile == 1) { src = Al; pitch = apitch; col = acol; grow = b0 + row; }
        else if (tile == 2) { src = Bh; pitch = bpitch; col = bcol; grow = jbase + row; }
        else                { src = Bl; pitch = bpitch; col = bcol; grow = jbase + row; }
        cp16(sbuf + tile * TILE_B + sw_off(row, seg),
             src + (size_t)grow * pitch + col + seg * 8);
    }
}

template <int LAYER>
__global__ void __launch_bounds__(256, 1) lstm_step(int t, const int* __restrict__ data,
                                                    float* __restrict__ out)
{
    extern __shared__ __align__(1024) char smem[];
    constexpr int NCH = LAYER ? 24 : 8;
    const int tid  = threadIdx.x;
    const int lane = tid & 31;
    const int warp = tid >> 5;
    const int wm   = warp >> 2;       // 0..1 -> 64 batch rows
    const int wn   = warp & 3;        // 0..3 -> 32 gate cols
    const int ntile = blockIdx.x;     // 0..7
    const int mtile = blockIdx.y;     // 0..31
    const int cell  = blockIdx.z;
    const int b0    = mtile * 128;
    const int jbase = ntile * 128;
    const uint32_t sb = smem_u32(smem);

    float acc[4][4][4];
#pragma unroll
    for (int mf = 0; mf < 4; ++mf)
#pragma unroll
        for (int nf = 0; nf < 4; ++nf)
#pragma unroll
            for (int q = 0; q < 4; ++q) acc[mf][nf][q] = 0.f;

    issue_chunk_loads<LAYER>(t, cell, b0, jbase, 0, sb, tid);
    CP_COMMIT();

    for (int kc = 0; kc < NCH; ++kc) {
        if (kc + 1 < NCH) {
            issue_chunk_loads<LAYER>(t, cell, b0, jbase, kc + 1, sb + ((kc + 1) & 1) * BUF_B, tid);
            CP_COMMIT();
            CP_WAIT(1);
        } else {
            CP_WAIT(0);
        }
        __syncthreads();

        const uint32_t abase = sb + (kc & 1) * BUF_B;
#pragma unroll
        for (int kk = 0; kk < 2; ++kk) {
            uint32_t ahi[4][4], alo[4][4];
#pragma unroll
            for (int mf = 0; mf < 4; ++mf) {
                int row = wm * 64 + mf * 16 + (lane & 15);
                int seg = kk * 2 + (lane >> 4);
                uint32_t a = abase + sw_off(row, seg);
                ldsm4(ahi[mf], a);
                ldsm4(alo[mf], a + TILE_B);
            }
            uint32_t bhi[4][2], blo[4][2];
#pragma unroll
            for (int p = 0; p < 2; ++p) {
                int row = wn * 32 + p * 16 + ((lane >> 4) & 1) * 8 + (lane & 7);
                int seg = kk * 2 + ((lane >> 3) & 1);
                uint32_t a = abase + 2 * TILE_B + sw_off(row, seg);
                uint32_t r[4];
                ldsm4(r, a);
                bhi[2 * p][0] = r[0]; bhi[2 * p][1] = r[1];
                bhi[2 * p + 1][0] = r[2]; bhi[2 * p + 1][1] = r[3];
                ldsm4(r, a + TILE_B);
                blo[2 * p][0] = r[0]; blo[2 * p][1] = r[1];
                blo[2 * p + 1][0] = r[2]; blo[2 * p + 1][1] = r[3];
            }
#pragma unroll
            for (int mf = 0; mf < 4; ++mf)
#pragma unroll
                for (int nf = 0; nf < 4; ++nf)
                    mma16816(acc[mf][nf], ahi[mf], bhi[nf]);
#pragma unroll
            for (int mf = 0; mf < 4; ++mf)
#pragma unroll
                for (int nf = 0; nf < 4; ++nf)
                    mma16816(acc[mf][nf], alo[mf], bhi[nf]);
#pragma unroll
            for (int mf = 0; mf < 4; ++mf)
#pragma unroll
                for (int nf = 0; nf < 4; ++nf)
                    mma16816(acc[mf][nf], ahi[mf], blo[nf]);
        }
        __syncthreads();
    }

    // ---------------- epilogue: accum -> SMEM gates [128][GP] ----------------
    float* gsm = (float*)smem;
    {
        int r0 = wm * 64 + (lane >> 2);
        int c0 = wn * 32 + (lane & 3) * 2;
#pragma unroll
        for (int mf = 0; mf < 4; ++mf)
#pragma unroll
            for (int nf = 0; nf < 4; ++nf) {
                int r = r0 + mf * 16, c = c0 + nf * 8;
                gsm[r * GP + c]           = acc[mf][nf][0];
                gsm[r * GP + c + 1]       = acc[mf][nf][1];
                gsm[(r + 8) * GP + c]     = acc[mf][nf][2];
                gsm[(r + 8) * GP + c + 1] = acc[mf][nf][3];
            }
    }
    __syncthreads();

    if (tid < 128) {
        const int b  = b0 + tid;
        const int cl = LAYER * 2 + cell;
        const int u0 = ntile * 32;
        const float* bias = (LAYER ? g_b1r[cell] : g_b0r[cell]) + jbase;
        const float* wrow = nullptr;
        if (LAYER == 0) {
            int pos = __ldg(&data[b * SEQN + t]);
            if (pos >= 0) wrow = &g_Wt0r[cell][pos][jbase];
        }
        const float* grow = gsm + tid * GP;

        uint32_t phi[16], plo[16];
        float houtf[32];
#pragma unroll
        for (int u = 0; u < 32; ++u) {
            float gi = grow[4 * u + 0] + bias[4 * u + 0];
            float gf = grow[4 * u + 1] + bias[4 * u + 1];
            float gz = grow[4 * u + 2] + bias[4 * u + 2];
            float go = grow[4 * u + 3] + bias[4 * u + 3];
            if (LAYER == 0 && wrow) {
                gi += wrow[4 * u + 0]; gf += wrow[4 * u + 1];
                gz += wrow[4 * u + 2]; go += wrow[4 * u + 3];
            }
            float cold = g_cT[cl][u0 + u][b];
            float cn = sigf(gf) * cold + sigf(gi) * tanhf(gz);
            float hn = sigf(go) * tanhf(cn);
            g_cT[cl][u0 + u][b] = cn;

            __nv_bfloat16 hh, hl;
            split_bf16(hn, hh, hl);
            reinterpret_cast<__nv_bfloat16*>(phi)[u] = hh;
            reinterpret_cast<__nv_bfloat16*>(plo)[u] = hl;
            houtf[u] = hn;
        }

        if (LAYER == 0) {
            __nv_bfloat16* dh = &g_X0hi[t + 1][b][cell * HID + u0];
            __nv_bfloat16* dl = &g_X0lo[t + 1][b][cell * HID + u0];
#pragma unroll
            for (int w = 0; w < 4; ++w) {
                reinterpret_cast<uint4*>(dh)[w] = reinterpret_cast<uint4*>(phi)[w];
                reinterpret_cast<uint4*>(dl)[w] = reinterpret_cast<uint4*>(plo)[w];
            }
        } else {
            float* o = out + ((size_t)b * SEQN + t) * 512 + cell * HID + u0;
#pragma unroll
            for (int w = 0; w < 8; ++w)
                reinterpret_cast<float4*>(o)[w] = reinterpret_cast<float4*>(houtf)[w];
            int pn = (t + 1) & 1;
            __nv_bfloat16* dh = &g_H1hi[pn][cell][b][u0];
            __nv_bfloat16* dl = &g_H1lo[pn][cell][b][u0];
#pragma unroll
            for (int w = 0; w < 4; ++w) {
                reinterpret_cast<uint4*>(dh)[w] = reinterpret_cast<uint4*>(phi)[w];
                reinterpret_cast<uint4*>(dl)[w] = reinterpret_cast<uint4*>(plo)[w];
            }
        }
    }
}

// ---------------- launch ----------------
extern "C" void kernel_launch(void* const* d_in, const int* in_sizes, int n_in,
                              void* d_out, int out_size)
{
    const int*   data = (const int*)  d_in[0];
    const float* h0   = (const float*)d_in[1];
    const float* c0   = (const float*)d_in[2];
    const float* Wih0 = (const float*)d_in[3];
    const float* Whh0 = (const float*)d_in[4];
    const float* bih0 = (const float*)d_in[5];
    const float* bhh0 = (const float*)d_in[6];
    const float* Wih1 = (const float*)d_in[7];
    const float* Whh1 = (const float*)d_in[8];
    const float* bih1 = (const float*)d_in[9];
    const float* bhh1 = (const float*)d_in[10];
    float* out = (float*)d_out;

    cudaFuncSetAttribute(lstm_step<0>, cudaFuncAttributeMaxDynamicSharedMemorySize, SMEM_TOTAL);
    cudaFuncSetAttribute(lstm_step<1>, cudaFuncAttributeMaxDynamicSharedMemorySize, SMEM_TOTAL);

    prep_kernel<<<1024, 256>>>(h0, c0, Wih0, Whh0, bih0, bhh0, Wih1, Whh1, bih1, bhh1);

    dim3 grid(8, 32, 2);   // ntiles x mtiles x cells
    for (int t = 0; t < SEQN; ++t) {
        lstm_step<0><<<grid, 256, SMEM_TOTAL>>>(t, data, out);
        lstm_step<1><<<grid, 256, SMEM_TOTAL>>>(t, data, out);
    }
}

// round 10
// speedup vs baseline: 2.2288x; 1.3979x over previous
#include <cuda_runtime.h>
#include <cuda_bf16.h>
#include <math.h>
#include <stdint.h>

#define BATCH 4096
#define HID   256
#define SEQN  24
#define BOARD 361

// ---------------- device scratch (statics; no runtime allocs) ----------------
__device__ __nv_bfloat16 g_X0hi[SEQN + 1][BATCH][512];   // layer-0 outputs, hi (slot 0 = h0)
__device__ __nv_bfloat16 g_X0lo[SEQN + 1][BATCH][512];
__device__ __nv_bfloat16 g_H1hi[2][2][BATCH][HID];       // [parity][cell] layer-1 h state
__device__ __nv_bfloat16 g_H1lo[2][2][BATCH][HID];
__device__ __nv_bfloat16 g_W0hi[2][1024][256];           // Whh0, rows reordered j' = 4u+g
__device__ __nv_bfloat16 g_W0lo[2][1024][256];
__device__ __nv_bfloat16 g_W1hi[2][1024][768];           // [Wih1 | Whh1] concat on K
__device__ __nv_bfloat16 g_W1lo[2][1024][768];
__device__ float g_Wt0r[2][BOARD][1024];                 // transposed+reordered W_ih0 (fp32)
__device__ float g_b0r[2][1024];
__device__ float g_b1r[2][1024];
__device__ float g_cT[4][256][BATCH];                    // cell state [cell][unit][b]

// ---------------- PTX helpers (sm_80+ portable) ----------------
__device__ __forceinline__ uint32_t smem_u32(const void* p) {
    uint32_t a;
    asm("{ .reg .u64 t; cvta.to.shared.u64 t, %1; cvt.u32.u64 %0, t; }" : "=r"(a) : "l"(p));
    return a;
}
__device__ __forceinline__ void cp16(uint32_t dst, const void* src) {
    asm volatile("cp.async.cg.shared.global [%0], [%1], 16;" :: "r"(dst), "l"(src));
}
#define CP_COMMIT() asm volatile("cp.async.commit_group;" ::: "memory")
#define CP_WAIT(n)  asm volatile("cp.async.wait_group %0;" :: "n"(n) : "memory")

__device__ __forceinline__ void ldsm4(uint32_t* r, uint32_t addr) {
    asm volatile("ldmatrix.sync.aligned.m8n8.x4.shared.b16 {%0,%1,%2,%3}, [%4];"
                 : "=r"(r[0]), "=r"(r[1]), "=r"(r[2]), "=r"(r[3]) : "r"(addr));
}
__device__ __forceinline__ void mma16816(float* c, const uint32_t* a, const uint32_t* b) {
    asm volatile("mma.sync.aligned.m16n8k16.row.col.f32.bf16.bf16.f32 "
                 "{%0,%1,%2,%3}, {%4,%5,%6,%7}, {%8,%9}, {%0,%1,%2,%3};"
                 : "+f"(c[0]), "+f"(c[1]), "+f"(c[2]), "+f"(c[3])
                 : "r"(a[0]), "r"(a[1]), "r"(a[2]), "r"(a[3]), "r"(b[0]), "r"(b[1]));
}

__device__ __forceinline__ float sigf(float x) { return 1.0f / (1.0f + expf(-x)); }
__device__ __forceinline__ void split_bf16(float v, __nv_bfloat16& hi, __nv_bfloat16& lo) {
    hi = __float2bfloat16(v);
    lo = __float2bfloat16(v - __bfloat162float(hi));
}

// ---------------- prep ----------------
__global__ void prep_kernel(const float* __restrict__ h0, const float* __restrict__ c0,
                            const float* __restrict__ Wih0, const float* __restrict__ Whh0,
                            const float* __restrict__ bih0, const float* __restrict__ bhh0,
                            const float* __restrict__ Wih1, const float* __restrict__ Whh1,
                            const float* __restrict__ bih1, const float* __restrict__ bhh1)
{
    int t0 = blockIdx.x * blockDim.x + threadIdx.x;
    int stride = gridDim.x * blockDim.x;

    for (int i = t0; i < 2 * 1024 * 256; i += stride) {
        int cell = i >> 18, r = (i >> 8) & 1023, k = i & 255;
        int j = (r & 3) * 256 + (r >> 2);
        float v = Whh0[(size_t)cell * 1024 * 256 + (size_t)j * 256 + k];
        split_bf16(v, g_W0hi[cell][r][k], g_W0lo[cell][r][k]);
    }
    for (int i = t0; i < 2 * 1024 * 768; i += stride) {
        int cell = i / (1024 * 768), rem = i - cell * (1024 * 768);
        int r = rem / 768, k = rem - r * 768;
        int j = (r & 3) * 256 + (r >> 2);
        float v = (k < 512) ? Wih1[(size_t)cell * 1024 * 512 + (size_t)j * 512 + k]
                            : Whh1[(size_t)cell * 1024 * 256 + (size_t)j * 256 + (k - 512)];
        split_bf16(v, g_W1hi[cell][r][k], g_W1lo[cell][r][k]);
    }
    for (int i = t0; i < 2 * BOARD * 1024; i += stride) {
        int cell = i / (BOARD * 1024), rem = i - cell * (BOARD * 1024);
        int p = rem >> 10, jp = rem & 1023;
        int j = (jp & 3) * 256 + (jp >> 2);
        g_Wt0r[cell][p][jp] = Wih0[(size_t)cell * 1024 * BOARD + (size_t)j * BOARD + p];
    }
    for (int i = t0; i < 2 * 1024; i += stride) {
        int cell = i >> 10, jp = i & 1023;
        int j = (jp & 3) * 256 + (jp >> 2);
        g_b0r[cell][jp] = bih0[cell * 1024 + j] + bhh0[cell * 1024 + j];
        g_b1r[cell][jp] = bih1[cell * 1024 + j] + bhh1[cell * 1024 + j];
    }
    for (int i = t0; i < 2 * BATCH * HID; i += stride) {
        int cell = i / (BATCH * HID), rem = i - cell * (BATCH * HID);
        int b = rem >> 8, n = rem & 255;
        float v0 = h0[((size_t)cell * BATCH + b) * HID + n];
        split_bf16(v0, g_X0hi[0][b][cell * 256 + n], g_X0lo[0][b][cell * 256 + n]);
        float v1 = h0[((size_t)(2 + cell) * BATCH + b) * HID + n];
        split_bf16(v1, g_H1hi[0][cell][b][n], g_H1lo[0][cell][b][n]);
    }
    for (int i = t0; i < 4 * 256 * BATCH; i += stride) {
        int cl = i / (256 * BATCH), rem = i - cl * (256 * BATCH);
        int n = rem / BATCH, b = rem - n * BATCH;
        g_cT[cl][n][b] = c0[((size_t)cl * BATCH + b) * HID + n];
    }
}

// ---------------- fused step kernel ----------------
// One launch tl handles: layer-0 @ t=tl (blockIdx.x<8) and layer-1 @ t=tl-1 (>=8).
// CTA tile M=128 x N=128, 512 threads (16 warps, warp tile 32x32).
// K-chunk = 64 bf16 (128B rows, 8-seg swizzle), double-buffered.
// 3-term compensated bf16: Ahi*Bhi + Alo*Bhi + Ahi*Blo.
#define TILE_B   16384
#define BUF_B    (4 * TILE_B)
#define GP       129
#define SMEM_TOTAL (2 * BUF_B)   // 131072; gsm (66048) reuses buffer 0

__device__ __forceinline__ uint32_t sw_off(int row, int seg) {
    return (uint32_t)(row * 128 + ((seg ^ (row & 7)) << 4));
}

__device__ __forceinline__ void issue_chunk_loads(int layer, int t, int cell, int b0,
                                                  int jbase, int kc, uint32_t sbuf, int tid)
{
    const __nv_bfloat16 *Ah, *Al;
    int apitch, acol;
    if (layer == 0) {
        Ah = &g_X0hi[t][0][cell * HID]; Al = &g_X0lo[t][0][cell * HID];
        apitch = 512; acol = kc * 64;
    } else if (kc < 8) {
        Ah = &g_X0hi[t + 1][0][0]; Al = &g_X0lo[t + 1][0][0];
        apitch = 512; acol = kc * 64;
    } else {
        int p = t & 1;
        Ah = &g_H1hi[p][cell][0][0]; Al = &g_H1lo[p][cell][0][0];
        apitch = HID; acol = (kc - 8) * 64;
    }
    const __nv_bfloat16* Bh = layer ? &g_W1hi[cell][0][0] : &g_W0hi[cell][0][0];
    const __nv_bfloat16* Bl = layer ? &g_W1lo[cell][0][0] : &g_W0lo[cell][0][0];
    const int bpitch = layer ? 768 : 256, bcol = kc * 64;

#pragma unroll
    for (int it = 0; it < 8; ++it) {
        int id   = it * 512 + tid;
        int tile = id >> 10;        // 0..3
        int rem  = id & 1023;
        int row  = rem >> 3;        // 0..127
        int seg  = rem & 7;         // 0..7 (16B granules)
        const __nv_bfloat16* src;
        int pitch, col, grow;
        if (tile == 0)      { src = Ah; pitch = apitch; col = acol; grow = b0 + row; }
        else if (tile == 1) { src = Al; pitch = apitch; col = acol; grow = b0 + row; }
        else if (tile == 2) { src = Bh; pitch = bpitch; col = bcol; grow = jbase + row; }
        else                { src = Bl; pitch = bpitch; col = bcol; grow = jbase + row; }
        cp16(sbuf + tile * TILE_B + sw_off(row, seg),
             src + (size_t)grow * pitch + col + seg * 8);
    }
}

__global__ void __launch_bounds__(512, 1) lstm_step(int tl, const int* __restrict__ data,
                                                    float* __restrict__ out)
{
    extern __shared__ __align__(1024) char smem[];
    const int layer = blockIdx.x >> 3;
    if (layer == 0 && tl >= SEQN) return;
    if (layer == 1 && tl == 0) return;
    const int t = layer ? tl - 1 : tl;

    const int tid  = threadIdx.x;
    const int lane = tid & 31;
    const int warp = tid >> 5;
    const int wm   = warp >> 2;        // 0..3 -> 32 batch rows
    const int wn   = warp & 3;         // 0..3 -> 32 gate cols
    const int ntile = blockIdx.x & 7;
    const int mtile = blockIdx.y;
    const int cell  = blockIdx.z;
    const int b0    = mtile * 128;
    const int jbase = ntile * 128;
    const int NCH   = layer ? 12 : 4;
    const uint32_t sb = smem_u32(smem);

    float acc[2][4][4];
#pragma unroll
    for (int mf = 0; mf < 2; ++mf)
#pragma unroll
        for (int nf = 0; nf < 4; ++nf)
#pragma unroll
            for (int q = 0; q < 4; ++q) acc[mf][nf][q] = 0.f;

    issue_chunk_loads(layer, t, cell, b0, jbase, 0, sb, tid);
    CP_COMMIT();

    for (int kc = 0; kc < NCH; ++kc) {
        if (kc + 1 < NCH) {
            issue_chunk_loads(layer, t, cell, b0, jbase, kc + 1,
                              sb + ((kc + 1) & 1) * BUF_B, tid);
            CP_COMMIT();
            CP_WAIT(1);
        } else {
            CP_WAIT(0);
        }
        __syncthreads();

        const uint32_t abase = sb + (kc & 1) * BUF_B;
#pragma unroll
        for (int kk = 0; kk < 4; ++kk) {
            uint32_t ahi[2][4], alo[2][4];
#pragma unroll
            for (int mf = 0; mf < 2; ++mf) {
                int row = wm * 32 + mf * 16 + (lane & 15);
                int seg = kk * 2 + (lane >> 4);
                uint32_t a = abase + sw_off(row, seg);
                ldsm4(ahi[mf], a);
                ldsm4(alo[mf], a + TILE_B);
            }
            uint32_t bhi[4][2], blo[4][2];
#pragma unroll
            for (int p = 0; p < 2; ++p) {
                int row = wn * 32 + p * 16 + ((lane >> 4) & 1) * 8 + (lane & 7);
                int seg = kk * 2 + ((lane >> 3) & 1);
                uint32_t a = abase + 2 * TILE_B + sw_off(row, seg);
                uint32_t r[4];
                ldsm4(r, a);
                bhi[2 * p][0] = r[0]; bhi[2 * p][1] = r[1];
                bhi[2 * p + 1][0] = r[2]; bhi[2 * p + 1][1] = r[3];
                ldsm4(r, a + TILE_B);
                blo[2 * p][0] = r[0]; blo[2 * p][1] = r[1];
                blo[2 * p + 1][0] = r[2]; blo[2 * p + 1][1] = r[3];
            }
#pragma unroll
            for (int mf = 0; mf < 2; ++mf)
#pragma unroll
                for (int nf = 0; nf < 4; ++nf)
                    mma16816(acc[mf][nf], ahi[mf], bhi[nf]);
#pragma unroll
            for (int mf = 0; mf < 2; ++mf)
#pragma unroll
                for (int nf = 0; nf < 4; ++nf)
                    mma16816(acc[mf][nf], alo[mf], bhi[nf]);
#pragma unroll
            for (int mf = 0; mf < 2; ++mf)
#pragma unroll
                for (int nf = 0; nf < 4; ++nf)
                    mma16816(acc[mf][nf], ahi[mf], blo[nf]);
        }
        __syncthreads();
    }

    // ---------------- epilogue ----------------
    float* gsm = (float*)smem;
    {
        int r0 = wm * 32 + (lane >> 2);
        int c0 = wn * 32 + (lane & 3) * 2;
#pragma unroll
        for (int mf = 0; mf < 2; ++mf)
#pragma unroll
            for (int nf = 0; nf < 4; ++nf) {
                int r = r0 + mf * 16, c = c0 + nf * 8;
                gsm[r * GP + c]           = acc[mf][nf][0];
                gsm[r * GP + c + 1]       = acc[mf][nf][1];
                gsm[(r + 8) * GP + c]     = acc[mf][nf][2];
                gsm[(r + 8) * GP + c + 1] = acc[mf][nf][3];
            }
    }
    __syncthreads();

    {
        const int row = tid >> 2;          // 0..127 batch row
        const int sub = tid & 3;           // 8 units each
        const int b   = b0 + row;
        const int cl  = layer * 2 + cell;
        const int u0  = ntile * 32 + sub * 8;
        const float* bias = (layer ? g_b1r[cell] : g_b0r[cell]) + jbase + sub * 32;
        const float* wrow = nullptr;
        if (layer == 0) {
            int pos = __ldg(&data[b * SEQN + t]);
            if (pos >= 0) wrow = &g_Wt0r[cell][pos][jbase + sub * 32];
        }
        const float* grow = gsm + row * GP + sub * 32;

        uint32_t phi[4], plo[4];
        float houtf[8];
#pragma unroll
        for (int u = 0; u < 8; ++u) {
            float gi = grow[4 * u + 0] + bias[4 * u + 0];
            float gf = grow[4 * u + 1] + bias[4 * u + 1];
            float gz = grow[4 * u + 2] + bias[4 * u + 2];
            float go = grow[4 * u + 3] + bias[4 * u + 3];
            if (wrow) {
                gi += wrow[4 * u + 0]; gf += wrow[4 * u + 1];
                gz += wrow[4 * u + 2]; go += wrow[4 * u + 3];
            }
            float cold = g_cT[cl][u0 + u][b];
            float cn = sigf(gf) * cold + sigf(gi) * tanhf(gz);
            float hn = sigf(go) * tanhf(cn);
            g_cT[cl][u0 + u][b] = cn;

            __nv_bfloat16 hh, hl;
            split_bf16(hn, hh, hl);
            reinterpret_cast<__nv_bfloat16*>(phi)[u] = hh;
            reinterpret_cast<__nv_bfloat16*>(plo)[u] = hl;
            houtf[u] = hn;
        }

        if (layer == 0) {
            *reinterpret_cast<uint4*>(&g_X0hi[t + 1][b][cell * HID + u0]) =
                *reinterpret_cast<uint4*>(phi);
            *reinterpret_cast<uint4*>(&g_X0lo[t + 1][b][cell * HID + u0]) =
                *reinterpret_cast<uint4*>(plo);
        } else {
            float* o = out + ((size_t)b * SEQN + t) * 512 + cell * HID + u0;
            reinterpret_cast<float4*>(o)[0] = reinterpret_cast<float4*>(houtf)[0];
            reinterpret_cast<float4*>(o)[1] = reinterpret_cast<float4*>(houtf)[1];
            int pn = (t + 1) & 1;
            *reinterpret_cast<uint4*>(&g_H1hi[pn][cell][b][u0]) =
                *reinterpret_cast<uint4*>(phi);
            *reinterpret_cast<uint4*>(&g_H1lo[pn][cell][b][u0]) =
                *reinterpret_cast<uint4*>(plo);
        }
    }
}

// ---------------- launch ----------------
extern "C" void kernel_launch(void* const* d_in, const int* in_sizes, int n_in,
                              void* d_out, int out_size)
{
    const int*   data = (const int*)  d_in[0];
    const float* h0   = (const float*)d_in[1];
    const float* c0   = (const float*)d_in[2];
    const float* Wih0 = (const float*)d_in[3];
    const float* Whh0 = (const float*)d_in[4];
    const float* bih0 = (const float*)d_in[5];
    const float* bhh0 = (const float*)d_in[6];
    const float* Wih1 = (const float*)d_in[7];
    const float* Whh1 = (const float*)d_in[8];
    const float* bih1 = (const float*)d_in[9];
    const float* bhh1 = (const float*)d_in[10];
    float* out = (float*)d_out;

    cudaFuncSetAttribute(lstm_step, cudaFuncAttributeMaxDynamicSharedMemorySize, SMEM_TOTAL);

    prep_kernel<<<1024, 256>>>(h0, c0, Wih0, Whh0, bih0, bhh0, Wih1, Whh1, bih1, bhh1);

    dim3 grid(16, 32, 2);   // [layer0 ntiles | layer1 ntiles] x mtiles x cells
    for (int tl = 0; tl <= SEQN; ++tl)
        lstm_step<<<grid, 512, SMEM_TOTAL>>>(tl, data, out);
}